// round 16
// baseline (speedup 1.0000x reference)
#include <cuda_runtime.h>
#include <math.h>
#include <cstdint>

#define ADAPTERS 40
#define CAPS 3
#define CLASS_DIM 200
#define IN_CH 600
#define BATCH 256
#define DHID 768
#define NFUSED (CAPS * CLASS_DIM)  // 600

// Scratch (static device arrays -- no allocation at runtime)
__device__ float g_xT[ADAPTERS * IN_CH * BATCH];             // [k][c][b], tf32-rounded
__device__ float g_P[CAPS * ADAPTERS * BATCH * CLASS_DIM];   // [n][k][b][d]
__device__ float g_V[CAPS * BATCH * CLASS_DIM];              // [n][b][d] flat

// ---------------------------------------------------------------------------
// Software RNE rounding to tf32 bit pattern (low 13 mantissa bits zero).
// The sm_103 mma.sync tf32 fallback REQUIRES tf32-clean inputs (R11: raw fp32
// bits -> 3.5e-2 error; pre-cleaned -> ~3e-4 floor).
// ---------------------------------------------------------------------------
__device__ __forceinline__ uint32_t tf32_rne_u(uint32_t u) {
    return (u + 0xFFFu + ((u >> 13) & 1u)) & 0xFFFFE000u;
}
__device__ __forceinline__ float tf32_rne(float v) {
    return __uint_as_float(tf32_rne_u(__float_as_uint(v)));
}

__device__ __forceinline__ void mma_tf32(float* c, const uint32_t a0, const uint32_t a1,
                                         const uint32_t a2, const uint32_t a3,
                                         const uint32_t b0, const uint32_t b1) {
    asm volatile(
        "mma.sync.aligned.m16n8k8.row.col.f32.tf32.tf32.f32 "
        "{%0,%1,%2,%3}, {%4,%5,%6,%7}, {%8,%9}, {%0,%1,%2,%3};"
        : "+f"(c[0]), "+f"(c[1]), "+f"(c[2]), "+f"(c[3])
        : "r"(a0), "r"(a1), "r"(a2), "r"(a3), "r"(b0), "r"(b1));
}

// ---------------------------------------------------------------------------
// Kernel 0: transpose x (b,k,c) -> xT (k,c,b), tf32-rounded on the way out
// ---------------------------------------------------------------------------
__global__ void k_transpose(const float* __restrict__ x, const int* __restrict__ tptr) {
    int k = blockIdx.x;
    if (k > *tptr) return;
    __shared__ float tile[32][33];
    int c0 = blockIdx.y * 32;
    int b0 = blockIdx.z * 32;
    int tx = threadIdx.x, ty = threadIdx.y;  // (32, 8)
#pragma unroll
    for (int i = 0; i < 4; i++) {
        int b = b0 + ty + i * 8;
        int c = c0 + tx;
        float v = 0.f;
        if (c < IN_CH) v = x[((size_t)b * ADAPTERS + k) * IN_CH + c];
        tile[ty + i * 8][tx] = v;
    }
    __syncthreads();
#pragma unroll
    for (int i = 0; i < 4; i++) {
        int c = c0 + ty + i * 8;
        int b = b0 + tx;
        if (c < IN_CH)
            g_xT[((size_t)k * IN_CH + c) * BATCH + b] = tf32_rne(tile[tx][ty + i * 8]);
    }
}

// ---------------------------------------------------------------------------
// Kernel 1: priors GEMM, tf32 mma, BK=24, BN=128, 256 threads (8 warps as
// 4m x 2n, warp tile 32x64). Halves A L2 re-streaming vs BN=64 (10->5
// n-blocks re-read each A slice). Per CTA (k<=t, mhalf, nblock):
// C[128x128] = A[128x600] @ B[600x128]. 25 outer steps, double-buffered.
// A,B smem [c][*] pitch 136 (fragment + STS phases conflict-free).
// ---------------------------------------------------------------------------
#define BKC 24
#define PITCH 136
#define AW (BKC * PITCH)   // 3264 words per buffer
#define NSTEP (IN_CH / BKC)  // 25
#define GEMM_SMEM_BYTES (4 * AW * 4)  // 52224

__global__ __launch_bounds__(256, 2) void k_gemm_mma(const float* __restrict__ rw,
                                                     const int* __restrict__ tptr) {
    int k = blockIdx.z;
    if (k > *tptr) return;
    int b0 = blockIdx.x * 128;
    int g0 = blockIdx.y * 128;

    extern __shared__ uint32_t S[];  // [2*AW A][2*AW B]

    int tid = threadIdx.x;
    int lane = tid & 31;
    int wid = tid >> 5;
    int mw = wid & 3;        // 0..3: 32-row m strip
    int nw = wid >> 2;       // 0..1: 64-col n strip
    int g = lane >> 2, tg = lane & 3;

    // A staging: 24 c-rows x 128 b; thread rows arow+8i (i<3)
    int arow = tid >> 5;          // 0..7
    int acol = (tid & 31) * 4;    // 0..124
    const float* ax = g_xT + ((size_t)k * IN_CH + arow) * BATCH + b0 + acol;

    // B staging: 24 c-rows x 128 fused-n; thread rows brow+8i (i<3)
    int brow = tid >> 5;          // 0..7
    int bcol = (tid & 31) * 4;    // 0..124
    int gn = g0 + bcol;
    bool bval = gn < NFUSED;
    int nr = bval ? (gn / CLASS_DIM) : 0;
    int dr = bval ? (gn - nr * CLASS_DIM) : 0;
    const float* bx = rw + (((size_t)(k * CAPS + nr)) * IN_CH + brow) * CLASS_DIM + dr;

    float acc[2][8][4];
#pragma unroll
    for (int i = 0; i < 2; i++)
#pragma unroll
        for (int j = 0; j < 8; j++)
#pragma unroll
            for (int q = 0; q < 4; q++) acc[i][j][q] = 0.f;

    uint4 va[3], vb[3];
    // Prologue: chunk 0
#pragma unroll
    for (int i = 0; i < 3; i++)
        va[i] = *reinterpret_cast<const uint4*>(ax + (size_t)(8 * i) * BATCH);
#pragma unroll
    for (int i = 0; i < 3; i++) {
        vb[i] = make_uint4(0, 0, 0, 0);
        if (bval) vb[i] = *reinterpret_cast<const uint4*>(bx + (size_t)(8 * i) * CLASS_DIM);
    }
    {
#pragma unroll
        for (int i = 0; i < 3; i++)
            *reinterpret_cast<uint4*>(&S[(arow + 8 * i) * PITCH + acol]) = va[i];
#pragma unroll
        for (int i = 0; i < 3; i++) {
            uint4 r;
            r.x = tf32_rne_u(vb[i].x); r.y = tf32_rne_u(vb[i].y);
            r.z = tf32_rne_u(vb[i].z); r.w = tf32_rne_u(vb[i].w);
            *reinterpret_cast<uint4*>(&S[2 * AW + (brow + 8 * i) * PITCH + bcol]) = r;
        }
    }

    for (int ct = 0; ct < NSTEP; ct++) {
        __syncthreads();
        bool more = (ct + 1 < NSTEP);
        if (more) {
            int c = (ct + 1) * BKC;
#pragma unroll
            for (int i = 0; i < 3; i++)
                va[i] = *reinterpret_cast<const uint4*>(ax + (size_t)(c + 8 * i) * BATCH);
            if (bval) {
#pragma unroll
                for (int i = 0; i < 3; i++)
                    vb[i] = *reinterpret_cast<const uint4*>(bx + (size_t)(c + 8 * i) * CLASS_DIM);
            }
        }

        int abuf = (ct & 1) * AW;
        int bbuf = 2 * AW + (ct & 1) * AW;

#pragma unroll
        for (int sub = 0; sub < 3; sub++) {
            int cb = sub * 8;
            // A fragments: rows mw*32 + i*16 + g (+8); cols cb+tg (+4)
            uint32_t ah0[2], ah1[2], ah2[2], ah3[2];
#pragma unroll
            for (int i = 0; i < 2; i++) {
                int m = mw * 32 + i * 16 + g;
                ah0[i] = S[abuf + (cb + tg) * PITCH + m];
                ah1[i] = S[abuf + (cb + tg) * PITCH + m + 8];
                ah2[i] = S[abuf + (cb + tg + 4) * PITCH + m];
                ah3[i] = S[abuf + (cb + tg + 4) * PITCH + m + 8];
            }
            // B fragments: cols nw*64 + j*8 + g; rows cb+tg (+4)
            uint32_t bh0[8], bh1[8];
#pragma unroll
            for (int j = 0; j < 8; j++) {
                int r = nw * 64 + j * 8 + g;
                bh0[j] = S[bbuf + (cb + tg) * PITCH + r];
                bh1[j] = S[bbuf + (cb + tg + 4) * PITCH + r];
            }
#pragma unroll
            for (int i = 0; i < 2; i++)
#pragma unroll
                for (int j = 0; j < 8; j++)
                    mma_tf32(acc[i][j], ah0[i], ah1[i], ah2[i], ah3[i], bh0[j], bh1[j]);
        }

        if (more) {
            int na = ((ct + 1) & 1) * AW;
            int nb = 2 * AW + ((ct + 1) & 1) * AW;
#pragma unroll
            for (int i = 0; i < 3; i++)
                *reinterpret_cast<uint4*>(&S[na + (arow + 8 * i) * PITCH + acol]) = va[i];
#pragma unroll
            for (int i = 0; i < 3; i++) {
                uint4 r;
                r.x = tf32_rne_u(vb[i].x); r.y = tf32_rne_u(vb[i].y);
                r.z = tf32_rne_u(vb[i].z); r.w = tf32_rne_u(vb[i].w);
                *reinterpret_cast<uint4*>(&S[nb + (brow + 8 * i) * PITCH + bcol]) = r;
            }
        }
    }

    // Epilogue: c0,c1 -> row g cols 2tg,2tg+1; c2,c3 -> row g+8
#pragma unroll
    for (int j = 0; j < 8; j++) {
        int gc = g0 + nw * 64 + j * 8 + tg * 2;
        if (gc < NFUSED) {
            int n = gc / CLASS_DIM, d = gc - n * CLASS_DIM;  // gc even -> pair in-region
            float* p = g_P + ((size_t)(n * ADAPTERS + k) * BATCH) * CLASS_DIM + d;
#pragma unroll
            for (int i = 0; i < 2; i++) {
                int mr = b0 + mw * 32 + i * 16 + g;
                *reinterpret_cast<float2*>(p + (size_t)mr * CLASS_DIM) =
                    make_float2(acc[i][j][0], acc[i][j][1]);
                *reinterpret_cast<float2*>(p + (size_t)(mr + 8) * CLASS_DIM) =
                    make_float2(acc[i][j][2], acc[i][j][3]);
            }
        }
    }
}

// ---------------------------------------------------------------------------
// Kernel 2: routing (R12 block version). Only k<=t; parallel warp softmax.
// ---------------------------------------------------------------------------
__global__ __launch_bounds__(256) void k_route(const int* __restrict__ tptr,
                                               const float* __restrict__ tsv) {
    __shared__ float Ps[ADAPTERS][CLASS_DIM];
    __shared__ float tsvv[ADAPTERS], maskv[ADAPTERS];
    __shared__ float l[ADAPTERS], probs[ADAPTERS];
    __shared__ float vote[CLASS_DIM], outv[CLASS_DIM];
    __shared__ float coef_s;

    int b = blockIdx.x, n = blockIdx.y;
    int tid = threadIdx.x;
    int t = *tptr;
    int kc = t + 1;

    const float* Pb = g_P + ((size_t)(n * ADAPTERS) * BATCH + b) * CLASS_DIM;
    int nf4 = kc * (CLASS_DIM / 4);
    for (int q = tid; q < nf4; q += 256) {
        int k = q / (CLASS_DIM / 4);
        int r = q - k * (CLASS_DIM / 4);
        float4 v = *reinterpret_cast<const float4*>(Pb + (size_t)k * BATCH * CLASS_DIM + r * 4);
        *reinterpret_cast<float4*>(&Ps[k][r * 4]) = v;
    }
    if (tid < ADAPTERS) {
        float tv = tsv[t * ADAPTERS + tid];
        tsvv[tid] = tv;
        maskv[tid] = (tv == 0.f) ? -10000.f : 0.f;
        l[tid] = 0.f;
    }
    __syncthreads();

    int wrp = tid >> 5, lane = tid & 31;

    for (int it = 0; it < 3; it++) {
        if (tid < 32) {
            float v0 = (tid < kc) ? fmaf(l[tid], tsvv[tid], maskv[tid]) : -3.0e38f;
            float v1 = (tid + 32 < kc) ? fmaf(l[tid + 32], tsvv[tid + 32], maskv[tid + 32]) : -3.0e38f;
            float mx = fmaxf(v0, v1);
#pragma unroll
            for (int o = 16; o > 0; o >>= 1) mx = fmaxf(mx, __shfl_xor_sync(0xffffffff, mx, o));
            float e0 = (tid < kc) ? expf(v0 - mx) : 0.f;
            float e1 = (tid + 32 < kc) ? expf(v1 - mx) : 0.f;
            float sm = e0 + e1;
#pragma unroll
            for (int o = 16; o > 0; o >>= 1) sm += __shfl_xor_sync(0xffffffff, sm, o);
            float inv = 1.f / sm;
            if (tid < kc) probs[tid] = e0 * inv;
            if (tid + 32 < kc) probs[tid + 32] = e1 * inv;
        }
        __syncthreads();

        if (tid < CLASS_DIM) {
            float v = 0.f;
            for (int kk = 0; kk < kc; kk++) v = fmaf(probs[kk], Ps[kk][tid], v);
            vote[tid] = v;
        }
        __syncthreads();
        if (it == 2) break;

        if (tid < 32) {
            float p = 0.f;
            for (int d = tid; d < CLASS_DIM; d += 32) {
                float v = vote[d];
                p = fmaf(v, v, p);
            }
#pragma unroll
            for (int o = 16; o > 0; o >>= 1) p += __shfl_xor_sync(0xffffffff, p, o);
            if (tid == 0) coef_s = sqrtf(p) / (1.f + p);
        }
        __syncthreads();
        if (tid < CLASS_DIM) outv[tid] = vote[tid] * coef_s;
        __syncthreads();

        for (int kk = wrp; kk < kc; kk += 8) {
            float p = 0.f;
            for (int d = lane; d < CLASS_DIM; d += 32) p = fmaf(Ps[kk][d], outv[d], p);
#pragma unroll
            for (int o = 16; o > 0; o >>= 1) p += __shfl_xor_sync(0xffffffff, p, o);
            if (lane == 0) l[kk] += p;
        }
        __syncthreads();
    }

    if (tid < CLASS_DIM) g_V[((size_t)n * BATCH + b) * CLASS_DIM + tid] = vote[tid];
}

// ---------------------------------------------------------------------------
// Kernel 3: expansion. Register-resident gated coefficients; streaming stores.
// ---------------------------------------------------------------------------
#define EXP_SPLIT 8
#define EXP_ROWS (CLASS_DIM / EXP_SPLIT)  // 25

__global__ __launch_bounds__(192) void k_expand(const int* __restrict__ tptr,
                                                const float* __restrict__ s_ptr,
                                                const float* __restrict__ W,
                                                const float* __restrict__ bvec,
                                                const float* __restrict__ el,
                                                float* __restrict__ out) {
    __shared__ float h[CLASS_DIM * CAPS];

    int b2 = blockIdx.x;
    int d2_0 = blockIdx.y * EXP_ROWS;
    int tid = threadIdx.x;
    int t = *tptr;
    float s = s_ptr[0];

    for (int idx = tid; idx < CLASS_DIM * CAPS; idx += 192)
        h[idx] = g_V[(size_t)b2 * (CLASS_DIM * CAPS) + idx];

    int j = tid * 4;
    float4 e4 = *reinterpret_cast<const float4*>(el + (size_t)t * DHID + j);
    float4 b4 = *reinterpret_cast<const float4*>(bvec + j);
    float g0 = 1.f / (1.f + expf(-s * e4.x));
    float g1 = 1.f / (1.f + expf(-s * e4.y));
    float g2 = 1.f / (1.f + expf(-s * e4.z));
    float g3 = 1.f / (1.f + expf(-s * e4.w));
    float4 w0 = *reinterpret_cast<const float4*>(W + j * 3);
    float4 w1 = *reinterpret_cast<const float4*>(W + j * 3 + 4);
    float4 w2 = *reinterpret_cast<const float4*>(W + j * 3 + 8);
    float4 c0 = make_float4(w0.x * g0, w0.y * g0, w0.z * g0, b4.x * g0);
    float4 c1 = make_float4(w0.w * g1, w1.x * g1, w1.y * g1, b4.y * g1);
    float4 c2 = make_float4(w1.z * g2, w1.w * g2, w2.x * g2, b4.z * g2);
    float4 c3 = make_float4(w2.y * g3, w2.z * g3, w2.w * g3, b4.w * g3);
    __syncthreads();

    float* ob = out + (size_t)b2 * CLASS_DIM * DHID + (size_t)d2_0 * DHID + j;
    const float* hp = h + d2_0 * 3;
#pragma unroll 5
    for (int r = 0; r < EXP_ROWS; r++) {
        float h0 = hp[0], h1 = hp[1], h2 = hp[2];
        hp += 3;
        float4 o;
        o.x = fmaf(h0, c0.x, fmaf(h1, c0.y, fmaf(h2, c0.z, c0.w)));
        o.y = fmaf(h0, c1.x, fmaf(h1, c1.y, fmaf(h2, c1.z, c1.w)));
        o.z = fmaf(h0, c2.x, fmaf(h1, c2.y, fmaf(h2, c2.z, c2.w)));
        o.w = fmaf(h0, c3.x, fmaf(h1, c3.y, fmaf(h2, c3.z, c3.w)));
        __stcs(reinterpret_cast<float4*>(ob), o);
        ob += DHID;
    }
}

// ---------------------------------------------------------------------------
extern "C" void kernel_launch(void* const* d_in, const int* in_sizes, int n_in,
                              void* d_out, int out_size) {
    const int* t = (const int*)d_in[0];
    const float* x = (const float*)d_in[1];
    const float* s = (const float*)d_in[2];
    const float* rw = (const float*)d_in[3];
    const float* W = (const float*)d_in[4];
    const float* bb = (const float*)d_in[5];
    const float* el = (const float*)d_in[6];
    const float* tsv = (const float*)d_in[7];
    float* out = (float*)d_out;

    cudaFuncSetAttribute(k_gemm_mma, cudaFuncAttributeMaxDynamicSharedMemorySize,
                         GEMM_SMEM_BYTES);

    k_transpose<<<dim3(ADAPTERS, (IN_CH + 31) / 32, BATCH / 32), dim3(32, 8)>>>(x, t);
    k_gemm_mma<<<dim3(2, (NFUSED + 127) / 128, ADAPTERS), 256, GEMM_SMEM_BYTES>>>(rw, t);
    k_route<<<dim3(BATCH, CAPS), 256>>>(t, tsv);
    k_expand<<<dim3(BATCH, EXP_SPLIT), 192>>>(t, s, W, bb, el, out);
}

// round 17
// speedup vs baseline: 1.0224x; 1.0224x over previous
#include <cuda_runtime.h>
#include <math.h>
#include <cstdint>

#define ADAPTERS 40
#define CAPS 3
#define CLASS_DIM 200
#define IN_CH 600
#define BATCH 256
#define DHID 768
#define NFUSED (CAPS * CLASS_DIM)  // 600

// Scratch (static device arrays -- no allocation at runtime)
__device__ float g_xT[ADAPTERS * IN_CH * BATCH];             // [k][c][b], tf32-rounded
__device__ float g_P[CAPS * ADAPTERS * BATCH * CLASS_DIM];   // [n][k][b][d]
__device__ float g_V[CAPS * BATCH * CLASS_DIM];              // [n][b][d] flat

// ---------------------------------------------------------------------------
// Software RNE rounding to tf32 bit pattern (low 13 mantissa bits zero).
// The sm_103 mma.sync tf32 fallback REQUIRES tf32-clean inputs (R11: raw fp32
// bits -> 3.5e-2 error; pre-cleaned -> ~3e-4 floor).
// ---------------------------------------------------------------------------
__device__ __forceinline__ uint32_t tf32_rne_u(uint32_t u) {
    return (u + 0xFFFu + ((u >> 13) & 1u)) & 0xFFFFE000u;
}
__device__ __forceinline__ float tf32_rne(float v) {
    return __uint_as_float(tf32_rne_u(__float_as_uint(v)));
}

__device__ __forceinline__ void mma_tf32(float* c, const uint32_t a0, const uint32_t a1,
                                         const uint32_t a2, const uint32_t a3,
                                         const uint32_t b0, const uint32_t b1) {
    asm volatile(
        "mma.sync.aligned.m16n8k8.row.col.f32.tf32.tf32.f32 "
        "{%0,%1,%2,%3}, {%4,%5,%6,%7}, {%8,%9}, {%0,%1,%2,%3};"
        : "+f"(c[0]), "+f"(c[1]), "+f"(c[2]), "+f"(c[3])
        : "r"(a0), "r"(a1), "r"(a2), "r"(a3), "r"(b0), "r"(b1));
}

// ---------------------------------------------------------------------------
// Kernel 0: transpose x (b,k,c) -> xT (k,c,b), tf32-rounded on the way out
// ---------------------------------------------------------------------------
__global__ void k_transpose(const float* __restrict__ x, const int* __restrict__ tptr) {
    int k = blockIdx.x;
    if (k > *tptr) return;
    __shared__ float tile[32][33];
    int c0 = blockIdx.y * 32;
    int b0 = blockIdx.z * 32;
    int tx = threadIdx.x, ty = threadIdx.y;  // (32, 8)
#pragma unroll
    for (int i = 0; i < 4; i++) {
        int b = b0 + ty + i * 8;
        int c = c0 + tx;
        float v = 0.f;
        if (c < IN_CH) v = x[((size_t)b * ADAPTERS + k) * IN_CH + c];
        tile[ty + i * 8][tx] = v;
    }
    __syncthreads();
#pragma unroll
    for (int i = 0; i < 4; i++) {
        int c = c0 + ty + i * 8;
        int b = b0 + tx;
        if (c < IN_CH)
            g_xT[((size_t)k * IN_CH + c) * BATCH + b] = tf32_rne(tile[tx][ty + i * 8]);
    }
}

// ---------------------------------------------------------------------------
// Kernel 1: priors GEMM (R15 config -- measured GEMM ~29us). tf32 mma,
// BK=24 (3 k-steps per barrier), BM=128, BN=64, 128 threads, 3 CTAs/SM.
// Per CTA (k<=t, mhalf, nblock): C[128x64] = A[128x600] @ B[600x64].
// 25 outer steps; per step: 6 A-uint4 + 3 B-uint4 staged per thread.
// B direct from rw, tf32-rounded at STS. Conflict-free layouts.
// ---------------------------------------------------------------------------
#define BKC 24
#define PITCHA 136
#define PITCHB 72
#define AWORDS (BKC * PITCHA)   // 3264
#define BWORDS (BKC * PITCHB)   // 1728
#define NSTEP (IN_CH / BKC)     // 25

__global__ __launch_bounds__(128, 3) void k_gemm_mma(const float* __restrict__ rw,
                                                     const int* __restrict__ tptr) {
    int k = blockIdx.z;
    if (k > *tptr) return;
    int b0 = blockIdx.x * 128;
    int g0 = blockIdx.y * 64;

    __shared__ uint32_t S[2 * AWORDS + 2 * BWORDS];  // ~39.9 KB

    int tid = threadIdx.x;
    int lane = tid & 31;
    int wid = tid >> 5;
    int mw = wid & 1, nw = wid >> 1;
    int g = lane >> 2, tg = lane & 3;

    // A staging: 24 c-rows x 128 b, rows arow+4i (i<6), from g_xT
    int arow = tid >> 5;          // 0..3
    int acol = (tid & 31) * 4;    // 0..124
    const float* ax = g_xT + ((size_t)k * IN_CH + arow) * BATCH + b0 + acol;

    // B staging: 24 c-rows x 64 fused-n cols, rows crow+8i (i<3), from rw
    int crow = tid >> 4;          // 0..7
    int bcol = (tid & 15) * 4;    // 0..60
    int gn = g0 + bcol;
    bool bval = gn < NFUSED;
    int nr = bval ? (gn / CLASS_DIM) : 0;
    int dr = bval ? (gn - nr * CLASS_DIM) : 0;
    const float* bx = rw + (((size_t)(k * CAPS + nr)) * IN_CH + crow) * CLASS_DIM + dr;

    float acc[4][4][4];
#pragma unroll
    for (int i = 0; i < 4; i++)
#pragma unroll
        for (int j = 0; j < 4; j++)
#pragma unroll
            for (int q = 0; q < 4; q++) acc[i][j][q] = 0.f;

    uint4 va[6];
    uint4 vbv[3];
    // Prologue: chunk 0
#pragma unroll
    for (int i = 0; i < 6; i++)
        va[i] = *reinterpret_cast<const uint4*>(ax + (size_t)(4 * i) * BATCH);
#pragma unroll
    for (int i = 0; i < 3; i++) {
        vbv[i] = make_uint4(0, 0, 0, 0);
        if (bval) vbv[i] = *reinterpret_cast<const uint4*>(bx + (size_t)(8 * i) * CLASS_DIM);
    }
    {
#pragma unroll
        for (int i = 0; i < 6; i++)
            *reinterpret_cast<uint4*>(&S[(arow + 4 * i) * PITCHA + acol]) = va[i];
#pragma unroll
        for (int i = 0; i < 3; i++) {
            uint4 r;
            r.x = tf32_rne_u(vbv[i].x); r.y = tf32_rne_u(vbv[i].y);
            r.z = tf32_rne_u(vbv[i].z); r.w = tf32_rne_u(vbv[i].w);
            *reinterpret_cast<uint4*>(&S[2 * AWORDS + (crow + 8 * i) * PITCHB + bcol]) = r;
        }
    }

    for (int ct = 0; ct < NSTEP; ct++) {
        __syncthreads();
        bool more = (ct + 1 < NSTEP);
        if (more) {
            int c = (ct + 1) * BKC;
#pragma unroll
            for (int i = 0; i < 6; i++)
                va[i] = *reinterpret_cast<const uint4*>(ax + (size_t)(c + 4 * i) * BATCH);
            if (bval) {
#pragma unroll
                for (int i = 0; i < 3; i++)
                    vbv[i] = *reinterpret_cast<const uint4*>(bx + (size_t)(c + 8 * i) * CLASS_DIM);
            }
        }

        int abuf = (ct & 1) * AWORDS;
        int bbuf = 2 * AWORDS + (ct & 1) * BWORDS;

#pragma unroll
        for (int sub = 0; sub < 3; sub++) {
            int cb = sub * 8;
            uint32_t ah0[4], ah1[4], ah2[4], ah3[4];
#pragma unroll
            for (int i = 0; i < 4; i++) {
                int m = mw * 64 + i * 16 + g;
                ah0[i] = S[abuf + (cb + tg) * PITCHA + m];
                ah1[i] = S[abuf + (cb + tg) * PITCHA + m + 8];
                ah2[i] = S[abuf + (cb + tg + 4) * PITCHA + m];
                ah3[i] = S[abuf + (cb + tg + 4) * PITCHA + m + 8];
            }
            uint32_t bh0[4], bh1[4];
#pragma unroll
            for (int j = 0; j < 4; j++) {
                int r = nw * 32 + j * 8 + g;
                bh0[j] = S[bbuf + (cb + tg) * PITCHB + r];
                bh1[j] = S[bbuf + (cb + tg + 4) * PITCHB + r];
            }
#pragma unroll
            for (int i = 0; i < 4; i++)
#pragma unroll
                for (int j = 0; j < 4; j++)
                    mma_tf32(acc[i][j], ah0[i], ah1[i], ah2[i], ah3[i], bh0[j], bh1[j]);
        }

        if (more) {
            int na = ((ct + 1) & 1) * AWORDS;
            int nb = 2 * AWORDS + ((ct + 1) & 1) * BWORDS;
#pragma unroll
            for (int i = 0; i < 6; i++)
                *reinterpret_cast<uint4*>(&S[na + (arow + 4 * i) * PITCHA + acol]) = va[i];
#pragma unroll
            for (int i = 0; i < 3; i++) {
                uint4 r;
                r.x = tf32_rne_u(vbv[i].x); r.y = tf32_rne_u(vbv[i].y);
                r.z = tf32_rne_u(vbv[i].z); r.w = tf32_rne_u(vbv[i].w);
                *reinterpret_cast<uint4*>(&S[nb + (crow + 8 * i) * PITCHB + bcol]) = r;
            }
        }
    }

    // Epilogue: c0,c1 -> row g cols 2tg,2tg+1; c2,c3 -> row g+8
#pragma unroll
    for (int j = 0; j < 4; j++) {
        int gc = g0 + nw * 32 + j * 8 + tg * 2;
        if (gc < NFUSED) {
            int n = gc / CLASS_DIM, d = gc - n * CLASS_DIM;  // gc even -> pair in-region
            float* p = g_P + ((size_t)(n * ADAPTERS + k) * BATCH) * CLASS_DIM + d;
#pragma unroll
            for (int i = 0; i < 4; i++) {
                int mr = b0 + mw * 64 + i * 16 + g;
                *reinterpret_cast<float2*>(p + (size_t)mr * CLASS_DIM) =
                    make_float2(acc[i][j][0], acc[i][j][1]);
                *reinterpret_cast<float2*>(p + (size_t)(mr + 8) * CLASS_DIM) =
                    make_float2(acc[i][j][2], acc[i][j][3]);
            }
        }
    }
}

// ---------------------------------------------------------------------------
// Kernel 2: routing. Only k<=t; parallel warp softmax. The out = coef*vote
// materialization is folded into the agreement dot (coef * dot(P, vote)),
// deleting one phase + one barrier per update iteration.
// ---------------------------------------------------------------------------
__global__ __launch_bounds__(256) void k_route(const int* __restrict__ tptr,
                                               const float* __restrict__ tsv) {
    __shared__ float Ps[ADAPTERS][CLASS_DIM];
    __shared__ float tsvv[ADAPTERS], maskv[ADAPTERS];
    __shared__ float l[ADAPTERS], probs[ADAPTERS];
    __shared__ float vote[CLASS_DIM];
    __shared__ float coef_s;

    int b = blockIdx.x, n = blockIdx.y;
    int tid = threadIdx.x;
    int t = *tptr;
    int kc = t + 1;

    const float* Pb = g_P + ((size_t)(n * ADAPTERS) * BATCH + b) * CLASS_DIM;
    int nf4 = kc * (CLASS_DIM / 4);
    for (int q = tid; q < nf4; q += 256) {
        int k = q / (CLASS_DIM / 4);
        int r = q - k * (CLASS_DIM / 4);
        float4 v = *reinterpret_cast<const float4*>(Pb + (size_t)k * BATCH * CLASS_DIM + r * 4);
        *reinterpret_cast<float4*>(&Ps[k][r * 4]) = v;
    }
    if (tid < ADAPTERS) {
        float tv = tsv[t * ADAPTERS + tid];
        tsvv[tid] = tv;
        maskv[tid] = (tv == 0.f) ? -10000.f : 0.f;
        l[tid] = 0.f;
    }
    __syncthreads();

    int wrp = tid >> 5, lane = tid & 31;

    for (int it = 0; it < 3; it++) {
        if (tid < 32) {
            float v0 = (tid < kc) ? fmaf(l[tid], tsvv[tid], maskv[tid]) : -3.0e38f;
            float v1 = (tid + 32 < kc) ? fmaf(l[tid + 32], tsvv[tid + 32], maskv[tid + 32]) : -3.0e38f;
            float mx = fmaxf(v0, v1);
#pragma unroll
            for (int o = 16; o > 0; o >>= 1) mx = fmaxf(mx, __shfl_xor_sync(0xffffffff, mx, o));
            float e0 = (tid < kc) ? expf(v0 - mx) : 0.f;
            float e1 = (tid + 32 < kc) ? expf(v1 - mx) : 0.f;
            float sm = e0 + e1;
#pragma unroll
            for (int o = 16; o > 0; o >>= 1) sm += __shfl_xor_sync(0xffffffff, sm, o);
            float inv = 1.f / sm;
            if (tid < kc) probs[tid] = e0 * inv;
            if (tid + 32 < kc) probs[tid + 32] = e1 * inv;
        }
        __syncthreads();

        if (tid < CLASS_DIM) {
            float v = 0.f;
            for (int kk = 0; kk < kc; kk++) v = fmaf(probs[kk], Ps[kk][tid], v);
            vote[tid] = v;
        }
        __syncthreads();
        if (it == 2) break;

        // squash coefficient: sqrt(sq)/(1+sq)
        if (tid < 32) {
            float p = 0.f;
            for (int d = tid; d < CLASS_DIM; d += 32) {
                float v = vote[d];
                p = fmaf(v, v, p);
            }
#pragma unroll
            for (int o = 16; o > 0; o >>= 1) p += __shfl_xor_sync(0xffffffff, p, o);
            if (tid == 0) coef_s = sqrtf(p) / (1.f + p);
        }
        __syncthreads();

        // agreement: l[k] += coef * dot(P[k], vote)  (out materialization folded)
        float coef = coef_s;
        for (int kk = wrp; kk < kc; kk += 8) {
            float p = 0.f;
            for (int d = lane; d < CLASS_DIM; d += 32) p = fmaf(Ps[kk][d], vote[d], p);
#pragma unroll
            for (int o = 16; o > 0; o >>= 1) p += __shfl_xor_sync(0xffffffff, p, o);
            if (lane == 0) l[kk] = fmaf(coef, p, l[kk]);
        }
        __syncthreads();
    }

    if (tid < CLASS_DIM) g_V[((size_t)n * BATCH + b) * CLASS_DIM + tid] = vote[tid];
}

// ---------------------------------------------------------------------------
// Kernel 3: expansion. Register-resident gated coefficients; streaming stores;
// fully unrolled row loop (constant addressing, max store MLP).
// ---------------------------------------------------------------------------
#define EXP_SPLIT 8
#define EXP_ROWS (CLASS_DIM / EXP_SPLIT)  // 25

__global__ __launch_bounds__(192) void k_expand(const int* __restrict__ tptr,
                                                const float* __restrict__ s_ptr,
                                                const float* __restrict__ W,
                                                const float* __restrict__ bvec,
                                                const float* __restrict__ el,
                                                float* __restrict__ out) {
    __shared__ float h[CLASS_DIM * CAPS];

    int b2 = blockIdx.x;
    int d2_0 = blockIdx.y * EXP_ROWS;
    int tid = threadIdx.x;
    int t = *tptr;
    float s = s_ptr[0];

    for (int idx = tid; idx < CLASS_DIM * CAPS; idx += 192)
        h[idx] = g_V[(size_t)b2 * (CLASS_DIM * CAPS) + idx];

    int j = tid * 4;
    float4 e4 = *reinterpret_cast<const float4*>(el + (size_t)t * DHID + j);
    float4 b4 = *reinterpret_cast<const float4*>(bvec + j);
    float g0 = 1.f / (1.f + expf(-s * e4.x));
    float g1 = 1.f / (1.f + expf(-s * e4.y));
    float g2 = 1.f / (1.f + expf(-s * e4.z));
    float g3 = 1.f / (1.f + expf(-s * e4.w));
    float4 w0 = *reinterpret_cast<const float4*>(W + j * 3);
    float4 w1 = *reinterpret_cast<const float4*>(W + j * 3 + 4);
    float4 w2 = *reinterpret_cast<const float4*>(W + j * 3 + 8);
    float4 c0 = make_float4(w0.x * g0, w0.y * g0, w0.z * g0, b4.x * g0);
    float4 c1 = make_float4(w0.w * g1, w1.x * g1, w1.y * g1, b4.y * g1);
    float4 c2 = make_float4(w1.z * g2, w1.w * g2, w2.x * g2, b4.z * g2);
    float4 c3 = make_float4(w2.y * g3, w2.z * g3, w2.w * g3, b4.w * g3);
    __syncthreads();

    float* ob = out + (size_t)b2 * CLASS_DIM * DHID + (size_t)d2_0 * DHID + j;
    const float* hp = h + d2_0 * 3;
#pragma unroll
    for (int r = 0; r < EXP_ROWS; r++) {
        float h0 = hp[r * 3], h1 = hp[r * 3 + 1], h2 = hp[r * 3 + 2];
        float4 o;
        o.x = fmaf(h0, c0.x, fmaf(h1, c0.y, fmaf(h2, c0.z, c0.w)));
        o.y = fmaf(h0, c1.x, fmaf(h1, c1.y, fmaf(h2, c1.z, c1.w)));
        o.z = fmaf(h0, c2.x, fmaf(h1, c2.y, fmaf(h2, c2.z, c2.w)));
        o.w = fmaf(h0, c3.x, fmaf(h1, c3.y, fmaf(h2, c3.z, c3.w)));
        __stcs(reinterpret_cast<float4*>(ob + (size_t)r * DHID), o);
    }
}

// ---------------------------------------------------------------------------
extern "C" void kernel_launch(void* const* d_in, const int* in_sizes, int n_in,
                              void* d_out, int out_size) {
    const int* t = (const int*)d_in[0];
    const float* x = (const float*)d_in[1];
    const float* s = (const float*)d_in[2];
    const float* rw = (const float*)d_in[3];
    const float* W = (const float*)d_in[4];
    const float* bb = (const float*)d_in[5];
    const float* el = (const float*)d_in[6];
    const float* tsv = (const float*)d_in[7];
    float* out = (float*)d_out;

    k_transpose<<<dim3(ADAPTERS, (IN_CH + 31) / 32, BATCH / 32), dim3(32, 8)>>>(x, t);
    k_gemm_mma<<<dim3(2, (NFUSED + 63) / 64, ADAPTERS), 128>>>(rw, t);
    k_route<<<dim3(BATCH, CAPS), 256>>>(t, tsv);
    k_expand<<<dim3(BATCH, EXP_SPLIT), 192>>>(t, s, W, bb, el, out);
}